// round 11
// baseline (speedup 1.0000x reference)
#include <cuda_runtime.h>
#include <cuda_bf16.h>
#include <stdint.h>

// ---------------------------------------------------------------------------
// Problem constants
// ---------------------------------------------------------------------------
#define BB   64
#define TT   2048
#define HID  128
#define BT   (BB * TT)         // 131072 sequence rows

// Scratch (device globals; no allocation allowed).
__device__ float g_xp[(size_t)BT * 1024];        // gate preacts fwd|bwd (512 MiB)
__device__ float g_out1[(size_t)BT * 256];       // layer-0 output seq (128 MiB)
// Fragment-packed bf16 hi/lo operand images for the layer-1 HMMA GEMM
__device__ __align__(256) unsigned char g_abuf[(size_t)1024 * 4 * 32768];
__device__ __align__(256) unsigned char g_wbuf[(size_t)8 * 4 * 32768];

// ---------------------------------------------------------------------------
// Helpers
// ---------------------------------------------------------------------------
__device__ __forceinline__ float sigmoid_(float x) {
    return 1.0f / (1.0f + __expf(-x));
}
__device__ __forceinline__ float tanh_(float x) {
    return 1.0f - 2.0f / (__expf(2.0f * x) + 1.0f);
}
__device__ __forceinline__ void split1(float v, unsigned short& h, unsigned short& l) {
    __nv_bfloat16 hb = __float2bfloat16(v);
    float hf = __bfloat162float(hb);
    __nv_bfloat16 lb = __float2bfloat16(v - hf);
    h = __bfloat16_as_ushort(hb);
    l = __bfloat16_as_ushort(lb);
}
__device__ __forceinline__ uint32_t pack2(unsigned short a, unsigned short b) {
    return (uint32_t)a | ((uint32_t)b << 16);
}

// ---------------------------------------------------------------------------
// Pre-pass: A image (from g_out1) in m16n8k16 A-fragment order, bf16 hi/lo.
// ---------------------------------------------------------------------------
__global__ __launch_bounds__(256)
void convA_kernel()
{
    const int mt = blockIdx.x, tid = threadIdx.x;
#pragma unroll
    for (int it = 0; it < 16; it++) {
        int tup = tid + 256 * it;
        int lane = tup & 31;
        int kb = (tup >> 5) & 3;
        int mb = (tup >> 7) & 7;
        int ch = (tup >> 10) & 3;
        int row0 = mt * 128 + mb * 16 + (lane >> 2);
        int col0 = ch * 64 + kb * 16 + 2 * (lane & 3);
        const float* base = g_out1;
        float2 p0 = *(const float2*)(base + (size_t)row0 * 256 + col0);
        float2 p1 = *(const float2*)(base + (size_t)(row0 + 8) * 256 + col0);
        float2 p2 = *(const float2*)(base + (size_t)row0 * 256 + col0 + 8);
        float2 p3 = *(const float2*)(base + (size_t)(row0 + 8) * 256 + col0 + 8);
        unsigned short h0a, l0a, h0b, l0b, h1a, l1a, h1b, l1b;
        unsigned short h2a, l2a, h2b, l2b, h3a, l3a, h3b, l3b;
        split1(p0.x, h0a, l0a); split1(p0.y, h0b, l0b);
        split1(p1.x, h1a, l1a); split1(p1.y, h1b, l1b);
        split1(p2.x, h2a, l2a); split1(p2.y, h2b, l2b);
        split1(p3.x, h3a, l3a); split1(p3.y, h3b, l3b);
        uint4 hi = make_uint4(pack2(h0a, h0b), pack2(h1a, h1b),
                              pack2(h2a, h2b), pack2(h3a, h3b));
        uint4 lo = make_uint4(pack2(l0a, l0b), pack2(l1a, l1b),
                              pack2(l2a, l2b), pack2(l3a, l3b));
        unsigned char* dst = g_abuf + ((size_t)(mt * 4 + ch)) * 32768
                           + ((mb * 4 + kb) * 32 + lane) * 16;
        *(uint4*)dst = hi;
        *(uint4*)(dst + 16384) = lo;
    }
}

// ---------------------------------------------------------------------------
// Pre-pass: W image in m16n8k16 B-fragment order, bf16 hi/lo.
// ---------------------------------------------------------------------------
__global__ __launch_bounds__(256)
void convW_kernel(const float* __restrict__ Wf, const float* __restrict__ Wb)
{
    const int nt = blockIdx.x, ch = blockIdx.y, tid = threadIdx.x;
    const float* W = (nt < 4) ? Wf : Wb;
    const int nbase = (nt & 3) * 128;
#pragma unroll
    for (int it = 0; it < 8; it++) {
        int tup = tid + 256 * it;
        int lane = tup & 31;
        int kb = (tup >> 5) & 3;
        int nb = (tup >> 7) & 15;
        int n = nbase + nb * 8 + (lane >> 2);
        int k0 = ch * 64 + kb * 16 + 2 * (lane & 3);
        float2 q0 = *(const float2*)(W + (size_t)n * 256 + k0);
        float2 q1 = *(const float2*)(W + (size_t)n * 256 + k0 + 8);
        unsigned short h0a, l0a, h0b, l0b, h1a, l1a, h1b, l1b;
        split1(q0.x, h0a, l0a); split1(q0.y, h0b, l0b);
        split1(q1.x, h1a, l1a); split1(q1.y, h1b, l1b);
        uint2 hi = make_uint2(pack2(h0a, h0b), pack2(h1a, h1b));
        uint2 lo = make_uint2(pack2(l0a, l0b), pack2(l1a, l1b));
        unsigned char* dst = g_wbuf + ((size_t)(nt * 4 + ch)) * 32768
                           + ((nb * 4 + kb) * 32 + lane) * 8;
        *(uint2*)dst = hi;
        *(uint2*)(dst + 16384) = lo;
    }
}

// ---------------------------------------------------------------------------
// Layer-1 projection via mma.sync split-bf16 (HMMA.16816). Unchanged from R8.
// ---------------------------------------------------------------------------
#define GEMM_SMEM 65536

__device__ __forceinline__ void mma16816(float* c, const uint4& a, const uint2& b) {
    asm volatile(
        "mma.sync.aligned.m16n8k16.row.col.f32.bf16.bf16.f32 "
        "{%0,%1,%2,%3}, {%4,%5,%6,%7}, {%8,%9}, {%0,%1,%2,%3};"
        : "+f"(c[0]), "+f"(c[1]), "+f"(c[2]), "+f"(c[3])
        : "r"(a.x), "r"(a.y), "r"(a.z), "r"(a.w), "r"(b.x), "r"(b.y));
}

__global__ __launch_bounds__(256, 2)
void gemm1_mma_kernel(const float* __restrict__ bihf, const float* __restrict__ bhhf,
                      const float* __restrict__ bihb, const float* __restrict__ bhhb)
{
    extern __shared__ __align__(16) unsigned char smem[];
    const int nt  = blockIdx.x;
    const int mt  = blockIdx.y;
    const int tid = threadIdx.x;
    const int lane = tid & 31;
    const int w    = tid >> 5;
    const int wm   = (w >> 2) * 4;
    const int wn   = (w & 3) * 4;

    float acc[4][4][4];
#pragma unroll
    for (int i = 0; i < 4; i++)
#pragma unroll
        for (int j = 0; j < 4; j++)
#pragma unroll
            for (int r = 0; r < 4; r++) acc[i][j][r] = 0.0f;

    for (int ch = 0; ch < 4; ch++) {
        {
            const uint4* sA = (const uint4*)(g_abuf + ((size_t)(mt * 4 + ch)) * 32768);
            uint4* dA = (uint4*)smem;
#pragma unroll
            for (int i = 0; i < 8; i++) dA[tid + 256 * i] = sA[tid + 256 * i];
            const uint4* sW = (const uint4*)(g_wbuf + ((size_t)(nt * 4 + ch)) * 32768);
            uint4* dW = (uint4*)(smem + 32768);
#pragma unroll
            for (int i = 0; i < 8; i++) dW[tid + 256 * i] = sW[tid + 256 * i];
        }
        __syncthreads();

        const uint4* Ah = (const uint4*)smem;
        const uint4* Al = (const uint4*)(smem + 16384);
        const uint2* Wh = (const uint2*)(smem + 32768);
        const uint2* Wl = (const uint2*)(smem + 49152);

#pragma unroll
        for (int kb = 0; kb < 4; kb++) {
            uint4 ah[4], al[4];
            uint2 wh[4], wl[4];
#pragma unroll
            for (int i = 0; i < 4; i++) {
                int idx = ((wm + i) * 4 + kb) * 32 + lane;
                ah[i] = Ah[idx];
                al[i] = Al[idx];
            }
#pragma unroll
            for (int j = 0; j < 4; j++) {
                int idx = ((wn + j) * 4 + kb) * 32 + lane;
                wh[j] = Wh[idx];
                wl[j] = Wl[idx];
            }
#pragma unroll
            for (int i = 0; i < 4; i++)
#pragma unroll
                for (int j = 0; j < 4; j++) {
                    mma16816(acc[i][j], ah[i], wh[j]);
                    mma16816(acc[i][j], ah[i], wl[j]);
                    mma16816(acc[i][j], al[i], wh[j]);
                }
        }
        __syncthreads();
    }

    const int mrow0 = mt * 128 + (w >> 2) * 64 + (lane >> 2);
    const int ncol0 = nt * 128 + (w & 3) * 32 + 2 * (lane & 3);
#pragma unroll
    for (int j = 0; j < 4; j++) {
        int n0 = ncol0 + j * 8;
        float b0, b1;
        if (n0 < 512) { b0 = bihf[n0] + bhhf[n0]; b1 = bihf[n0 + 1] + bhhf[n0 + 1]; }
        else { b0 = bihb[n0 - 512] + bhhb[n0 - 512]; b1 = bihb[n0 - 511] + bhhb[n0 - 511]; }
#pragma unroll
        for (int i = 0; i < 4; i++) {
            int m0 = mrow0 + i * 16;
            float2 v0 = make_float2(acc[i][j][0] + b0, acc[i][j][1] + b1);
            float2 v1 = make_float2(acc[i][j][2] + b0, acc[i][j][3] + b1);
            *(float2*)(g_xp + (size_t)m0 * 1024 + n0) = v0;
            *(float2*)(g_xp + (size_t)(m0 + 8) * 1024 + n0) = v1;
        }
    }
}

// ---------------------------------------------------------------------------
// Layer-0 projection GEMM (FFMA2; K=32). Unchanged.
// ---------------------------------------------------------------------------
#define BM  128
#define BN  128
#define BKK 16

__global__ __launch_bounds__(256)
void proj_gemm_kernel(const float* __restrict__ A, int K,
                      const float* __restrict__ Wf, const float* __restrict__ Wb,
                      const float* __restrict__ bihf, const float* __restrict__ bhhf,
                      const float* __restrict__ bihb, const float* __restrict__ bhhb)
{
    __shared__ __align__(16) float As[BKK * BM];
    __shared__ __align__(16) float Ws[BKK * BN];

    const int n0 = blockIdx.x * BN;
    const int m0 = blockIdx.y * BM;

    const float* Wsel; const float* bihS; const float* bhhS; int nb;
    if (n0 < 512) { Wsel = Wf; bihS = bihf; bhhS = bhhf; nb = n0; }
    else          { Wsel = Wb; bihS = bihb; bhhS = bhhb; nb = n0 - 512; }

    const int tid = threadIdx.x;
    const int tx = tid & 15;
    const int ty = tid >> 4;

    unsigned long long acc[8][4];
#pragma unroll
    for (int i = 0; i < 8; i++)
#pragma unroll
        for (int j = 0; j < 4; j++) acc[i][j] = 0ULL;

    for (int k0 = 0; k0 < K; k0 += BKK) {
#pragma unroll
        for (int it = 0; it < 2; it++) {
            int idx = tid + it * 256;
            int r = idx >> 2, c4 = idx & 3;
            float4 a4 = *(const float4*)(A + (size_t)(m0 + r) * K + k0 + c4 * 4);
            As[(c4 * 4 + 0) * BM + r] = a4.x;
            As[(c4 * 4 + 1) * BM + r] = a4.y;
            As[(c4 * 4 + 2) * BM + r] = a4.z;
            As[(c4 * 4 + 3) * BM + r] = a4.w;
        }
#pragma unroll
        for (int it = 0; it < 2; it++) {
            int idx = tid + it * 256;
            int n = idx >> 2, c4 = idx & 3;
            float4 w4 = *(const float4*)(Wsel + (size_t)(nb + n) * K + k0 + c4 * 4);
            Ws[(c4 * 4 + 0) * BN + n] = w4.x;
            Ws[(c4 * 4 + 1) * BN + n] = w4.y;
            Ws[(c4 * 4 + 2) * BN + n] = w4.z;
            Ws[(c4 * 4 + 3) * BN + n] = w4.w;
        }
        __syncthreads();

#pragma unroll
        for (int kk = 0; kk < BKK; kk++) {
            const float* arow = As + kk * BM + ty * 8;
            float4 av0 = *(const float4*)(arow);
            float4 av1 = *(const float4*)(arow + 4);
            float av[8] = {av0.x, av0.y, av0.z, av0.w, av1.x, av1.y, av1.z, av1.w};
            unsigned long long a2[8];
#pragma unroll
            for (int i = 0; i < 8; i++) {
                unsigned int ai = __float_as_uint(av[i]);
                asm("mov.b64 %0, {%1, %1};" : "=l"(a2[i]) : "r"(ai));
            }
            const unsigned long long* wrow =
                (const unsigned long long*)(Ws + kk * BN + tx * 8);
            unsigned long long b0 = wrow[0], b1 = wrow[1], b2 = wrow[2], b3 = wrow[3];
#pragma unroll
            for (int i = 0; i < 8; i++) {
                asm("fma.rn.f32x2 %0, %1, %2, %0;" : "+l"(acc[i][0]) : "l"(a2[i]), "l"(b0));
                asm("fma.rn.f32x2 %0, %1, %2, %0;" : "+l"(acc[i][1]) : "l"(a2[i]), "l"(b1));
                asm("fma.rn.f32x2 %0, %1, %2, %0;" : "+l"(acc[i][2]) : "l"(a2[i]), "l"(b2));
                asm("fma.rn.f32x2 %0, %1, %2, %0;" : "+l"(acc[i][3]) : "l"(a2[i]), "l"(b3));
            }
        }
        __syncthreads();
    }

    float bias[8];
#pragma unroll
    for (int j = 0; j < 8; j++) {
        int n = nb + tx * 8 + j;
        bias[j] = bihS[n] + bhhS[n];
    }
#pragma unroll
    for (int i = 0; i < 8; i++) {
        float out[8];
#pragma unroll
        for (int j2 = 0; j2 < 4; j2++) {
            unsigned int lo_u, hi_u;
            asm("mov.b64 {%0, %1}, %2;" : "=r"(lo_u), "=r"(hi_u) : "l"(acc[i][j2]));
            out[2 * j2 + 0] = __uint_as_float(lo_u) + bias[2 * j2 + 0];
            out[2 * j2 + 1] = __uint_as_float(hi_u) + bias[2 * j2 + 1];
        }
        float4* dst = (float4*)(g_xp + (size_t)(m0 + ty * 8 + i) * 1024 + n0 + tx * 8);
        dst[0] = make_float4(out[0], out[1], out[2], out[3]);
        dst[1] = make_float4(out[4], out[5], out[6], out[7]);
    }
}

// ---------------------------------------------------------------------------
// LSTM recurrent scan v4.
//   256 threads; thread = (u, kh). NPREG=22 pairs/gate in regs (176 regs,
//   ~25 regs slack for ptxas LDS pipelining), 10 pairs/gate in smem (80 KB).
//   h stored TWICE per parity (copy B at +16-word skew) -> kh0/kh1 LDS.128
//   broadcasts hit disjoint banks (1 wavefront). Both kh threads run the
//   butterfly + activations (redundantly) and store their own h copy;
//   each prefetches 2 of 4 gate preacts. One __syncthreads per step.
// ---------------------------------------------------------------------------
#define NPREG 22
#define NPSM  (32 - NPREG)                  // 10
#define WSM_ULL (4 * NPSM * 256)            // 10240 ull = 80 KiB
#define HPAR 272                            // copyA words 0..127, copyB 144..271
#define SCAN_SMEM (WSM_ULL * 8 + 2 * HPAR * 4)

__global__ __launch_bounds__(256, 1)
void lstm_scan_kernel(const float* __restrict__ WhhF,
                      const float* __restrict__ WhhB,
                      int writeSeq,
                      float* __restrict__ finalOut)
{
    extern __shared__ __align__(16) float smemf[];
    unsigned long long* Wsm = (unsigned long long*)smemf;   // [4*NPSM][256]
    float* hbuf = smemf + WSM_ULL * 2;                      // [2][HPAR]

    const int b   = blockIdx.x;
    const int dir = blockIdx.y;
    const int t   = threadIdx.x;
    const int u   = t >> 1;
    const int kh  = t & 1;
    const int K0  = kh * 64;
    const float* __restrict__ Whh = dir ? WhhB : WhhF;

    unsigned long long wr[4][NPREG];
#pragma unroll
    for (int g = 0; g < 4; g++) {
        const unsigned long long* row =
            (const unsigned long long*)(Whh + (size_t)(g * 128 + u) * HID + K0);
#pragma unroll
        for (int p = 0; p < NPREG; p++) wr[g][p] = row[p];
#pragma unroll
        for (int q = 0; q < NPSM; q++)
            Wsm[(g * NPSM + q) * 256 + t] = row[NPREG + q];
    }

    for (int i = t; i < 2 * HPAR; i += 256) hbuf[i] = 0.0f;

    // gate preacts: kh0 loads gates 0,1; kh1 loads gates 2,3 (for unit u)
    const size_t xbase = (size_t)b * TT * 1024 + (size_t)dir * 512
                       + (size_t)kh * 256 + u;
    const size_t obase = (size_t)b * TT * 256 + (size_t)dir * HID + u;

    float xvA, xvB;
    {
        int t0 = dir ? (TT - 1) : 0;
        const float* xp = g_xp + xbase + (size_t)t0 * 1024;
        xvA = xp[0]; xvB = xp[128];
    }

    // read base: kh0 -> copyA words 0..63; kh1 -> copyB words 208..271
    const int rdoff = kh ? (144 + 64) : 0;
    const int wroff = kh ? (144 + u) : u;

    __syncthreads();

    float cval = 0.0f, hval = 0.0f;
    int par = 0;

    for (int s = 0; s < TT; s++) {
        const int tcur = dir ? (TT - 1 - s) : s;

        float nxA, nxB;
        {
            int sn = (s + 1 < TT) ? (s + 1) : s;
            int tn = dir ? (TT - 1 - sn) : sn;
            const float* xpn = g_xp + xbase + (size_t)tn * 1024;
            nxA = xpn[0]; nxB = xpn[128];
        }

        const float* hc = hbuf + par * HPAR + rdoff;
        unsigned long long a0 = 0ULL, a1 = 0ULL, a2 = 0ULL, a3 = 0ULL;
#pragma unroll
        for (int i = 0; i < 16; i++) {
            ulonglong2 hv = *(const ulonglong2*)(hc + 4 * i);
            unsigned long long w0a, w0b, w0c, w0d, w1a, w1b, w1c, w1d;
            if (2 * i + 1 < NPREG) {
                w0a = wr[0][2 * i];     w1a = wr[0][2 * i + 1];
                w0b = wr[1][2 * i];     w1b = wr[1][2 * i + 1];
                w0c = wr[2][2 * i];     w1c = wr[2][2 * i + 1];
                w0d = wr[3][2 * i];     w1d = wr[3][2 * i + 1];
            } else {
                int q0 = 2 * i - NPREG;
                w0a = Wsm[(0 * NPSM + q0) * 256 + t];
                w1a = Wsm[(0 * NPSM + q0 + 1) * 256 + t];
                w0b = Wsm[(1 * NPSM + q0) * 256 + t];
                w1b = Wsm[(1 * NPSM + q0 + 1) * 256 + t];
                w0c = Wsm[(2 * NPSM + q0) * 256 + t];
                w1c = Wsm[(2 * NPSM + q0 + 1) * 256 + t];
                w0d = Wsm[(3 * NPSM + q0) * 256 + t];
                w1d = Wsm[(3 * NPSM + q0 + 1) * 256 + t];
            }
            asm("fma.rn.f32x2 %0, %1, %2, %0;" : "+l"(a0) : "l"(w0a), "l"(hv.x));
            asm("fma.rn.f32x2 %0, %1, %2, %0;" : "+l"(a1) : "l"(w0b), "l"(hv.x));
            asm("fma.rn.f32x2 %0, %1, %2, %0;" : "+l"(a2) : "l"(w0c), "l"(hv.x));
            asm("fma.rn.f32x2 %0, %1, %2, %0;" : "+l"(a3) : "l"(w0d), "l"(hv.x));
            asm("fma.rn.f32x2 %0, %1, %2, %0;" : "+l"(a0) : "l"(w1a), "l"(hv.y));
            asm("fma.rn.f32x2 %0, %1, %2, %0;" : "+l"(a1) : "l"(w1b), "l"(hv.y));
            asm("fma.rn.f32x2 %0, %1, %2, %0;" : "+l"(a2) : "l"(w1c), "l"(hv.y));
            asm("fma.rn.f32x2 %0, %1, %2, %0;" : "+l"(a3) : "l"(w1d), "l"(hv.y));
        }

        float s0, s1, s2, s3;
        {
            unsigned int lo, hi;
            asm("mov.b64 {%0, %1}, %2;" : "=r"(lo), "=r"(hi) : "l"(a0));
            s0 = __uint_as_float(lo) + __uint_as_float(hi);
            asm("mov.b64 {%0, %1}, %2;" : "=r"(lo), "=r"(hi) : "l"(a1));
            s1 = __uint_as_float(lo) + __uint_as_float(hi);
            asm("mov.b64 {%0, %1}, %2;" : "=r"(lo), "=r"(hi) : "l"(a2));
            s2 = __uint_as_float(lo) + __uint_as_float(hi);
            asm("mov.b64 {%0, %1}, %2;" : "=r"(lo), "=r"(hi) : "l"(a3));
            s3 = __uint_as_float(lo) + __uint_as_float(hi);
        }
        // add own gate preacts before the butterfly (each gate added once)
        if (kh == 0) { s0 += xvA; s1 += xvB; }
        else         { s2 += xvA; s3 += xvB; }

        s0 += __shfl_xor_sync(0xffffffffu, s0, 1);
        s1 += __shfl_xor_sync(0xffffffffu, s1, 1);
        s2 += __shfl_xor_sync(0xffffffffu, s2, 1);
        s3 += __shfl_xor_sync(0xffffffffu, s3, 1);

        // both kh threads compute activations (identical results)
        {
            float iv = sigmoid_(s0);
            float fv = sigmoid_(s1);
            float gv = tanh_(s2);
            float ov = sigmoid_(s3);
            cval = fv * cval + iv * gv;
            hval = ov * tanh_(cval);
            hbuf[(par ^ 1) * HPAR + wroff] = hval;   // kh0->copyA, kh1->copyB
            if (writeSeq && kh == 0)
                g_out1[obase + (size_t)tcur * 256] = hval;
        }
        __syncthreads();

        par ^= 1;
        xvA = nxA; xvB = nxB;
    }

    if (finalOut != nullptr && kh == 0)
        finalOut[(size_t)b * 256 + (size_t)dir * HID + u] = hval;
}

// ---------------------------------------------------------------------------
// kernel_launch
// ---------------------------------------------------------------------------
extern "C" void kernel_launch(void* const* d_in, const int* in_sizes, int n_in,
                              void* d_out, int out_size)
{
    const float* x       = (const float*)d_in[0];
    const float* Wih_l0f = (const float*)d_in[1];
    const float* Whh_l0f = (const float*)d_in[2];
    const float* bih_l0f = (const float*)d_in[3];
    const float* bhh_l0f = (const float*)d_in[4];
    const float* Wih_l0b = (const float*)d_in[5];
    const float* Whh_l0b = (const float*)d_in[6];
    const float* bih_l0b = (const float*)d_in[7];
    const float* bhh_l0b = (const float*)d_in[8];
    const float* Wih_l1f = (const float*)d_in[9];
    const float* Whh_l1f = (const float*)d_in[10];
    const float* bih_l1f = (const float*)d_in[11];
    const float* bhh_l1f = (const float*)d_in[12];
    const float* Wih_l1b = (const float*)d_in[13];
    const float* Whh_l1b = (const float*)d_in[14];
    const float* bih_l1b = (const float*)d_in[15];
    const float* bhh_l1b = (const float*)d_in[16];

    float* out = (float*)d_out;

    cudaFuncSetAttribute(lstm_scan_kernel,
                         cudaFuncAttributeMaxDynamicSharedMemorySize, SCAN_SMEM);
    cudaFuncSetAttribute(gemm1_mma_kernel,
                         cudaFuncAttributeMaxDynamicSharedMemorySize, GEMM_SMEM);

    // W hi/lo fragment images for layer-1 HMMA
    convW_kernel<<<dim3(8, 4), 256>>>(Wih_l1f, Wih_l1b);

    // Layer 0 input projection (FFMA2): x[BT,32] -> g_xp[BT,1024]
    proj_gemm_kernel<<<dim3(8, BT / BM), 256>>>(x, 32,
                                                Wih_l0f, Wih_l0b,
                                                bih_l0f, bhh_l0f, bih_l0b, bhh_l0b);

    // Layer 0 scan: g_xp -> g_out1[BT,256]
    lstm_scan_kernel<<<dim3(BB, 2), 256, SCAN_SMEM>>>(
        Whh_l0f, Whh_l0b, /*writeSeq=*/1, /*finalOut=*/nullptr);

    // A hi/lo fragment images from g_out1
    convA_kernel<<<1024, 256>>>();

    // Layer 1 projection via split-bf16 mma.sync -> g_xp[BT,1024]
    gemm1_mma_kernel<<<dim3(8, 1024), 256, GEMM_SMEM>>>(
        bih_l1f, bhh_l1f, bih_l1b, bhh_l1b);

    // Layer 1 scan: g_xp -> final hidden states in d_out[64,256]
    lstm_scan_kernel<<<dim3(BB, 2), 256, SCAN_SMEM>>>(
        Whh_l1f, Whh_l1b, /*writeSeq=*/0, /*finalOut=*/out);
}

// round 12
// speedup vs baseline: 1.0010x; 1.0010x over previous
#include <cuda_runtime.h>
#include <cuda_bf16.h>
#include <stdint.h>

// ---------------------------------------------------------------------------
// Problem constants
// ---------------------------------------------------------------------------
#define BB   64
#define TT   2048
#define HID  128
#define BT   (BB * TT)         // 131072 sequence rows

// Scratch (device globals; no allocation allowed).
__device__ float g_xp[(size_t)BT * 1024];        // gate preacts fwd|bwd (512 MiB)
__device__ float g_out1[(size_t)BT * 256];       // layer-0 output seq (128 MiB)
// Fragment-packed bf16 hi/lo operand images for the layer-1 HMMA GEMM
__device__ __align__(256) unsigned char g_abuf[(size_t)1024 * 4 * 32768];
__device__ __align__(256) unsigned char g_wbuf[(size_t)8 * 4 * 32768];

// ---------------------------------------------------------------------------
// Helpers
// ---------------------------------------------------------------------------
__device__ __forceinline__ float sigmoid_(float x) {
    return 1.0f / (1.0f + __expf(-x));
}
__device__ __forceinline__ float tanh_(float x) {
    return 1.0f - 2.0f / (__expf(2.0f * x) + 1.0f);
}
__device__ __forceinline__ void split1(float v, unsigned short& h, unsigned short& l) {
    __nv_bfloat16 hb = __float2bfloat16(v);
    float hf = __bfloat162float(hb);
    __nv_bfloat16 lb = __float2bfloat16(v - hf);
    h = __bfloat16_as_ushort(hb);
    l = __bfloat16_as_ushort(lb);
}
__device__ __forceinline__ uint32_t pack2(unsigned short a, unsigned short b) {
    return (uint32_t)a | ((uint32_t)b << 16);
}

// ---------------------------------------------------------------------------
// Pre-pass: A image (from g_out1) in m16n8k16 A-fragment order, bf16 hi/lo.
// ---------------------------------------------------------------------------
__global__ __launch_bounds__(256)
void convA_kernel()
{
    const int mt = blockIdx.x, tid = threadIdx.x;
#pragma unroll
    for (int it = 0; it < 16; it++) {
        int tup = tid + 256 * it;
        int lane = tup & 31;
        int kb = (tup >> 5) & 3;
        int mb = (tup >> 7) & 7;
        int ch = (tup >> 10) & 3;
        int row0 = mt * 128 + mb * 16 + (lane >> 2);
        int col0 = ch * 64 + kb * 16 + 2 * (lane & 3);
        const float* base = g_out1;
        float2 p0 = *(const float2*)(base + (size_t)row0 * 256 + col0);
        float2 p1 = *(const float2*)(base + (size_t)(row0 + 8) * 256 + col0);
        float2 p2 = *(const float2*)(base + (size_t)row0 * 256 + col0 + 8);
        float2 p3 = *(const float2*)(base + (size_t)(row0 + 8) * 256 + col0 + 8);
        unsigned short h0a, l0a, h0b, l0b, h1a, l1a, h1b, l1b;
        unsigned short h2a, l2a, h2b, l2b, h3a, l3a, h3b, l3b;
        split1(p0.x, h0a, l0a); split1(p0.y, h0b, l0b);
        split1(p1.x, h1a, l1a); split1(p1.y, h1b, l1b);
        split1(p2.x, h2a, l2a); split1(p2.y, h2b, l2b);
        split1(p3.x, h3a, l3a); split1(p3.y, h3b, l3b);
        uint4 hi = make_uint4(pack2(h0a, h0b), pack2(h1a, h1b),
                              pack2(h2a, h2b), pack2(h3a, h3b));
        uint4 lo = make_uint4(pack2(l0a, l0b), pack2(l1a, l1b),
                              pack2(l2a, l2b), pack2(l3a, l3b));
        unsigned char* dst = g_abuf + ((size_t)(mt * 4 + ch)) * 32768
                           + ((mb * 4 + kb) * 32 + lane) * 16;
        *(uint4*)dst = hi;
        *(uint4*)(dst + 16384) = lo;
    }
}

// ---------------------------------------------------------------------------
// Pre-pass: W image in m16n8k16 B-fragment order, bf16 hi/lo.
// ---------------------------------------------------------------------------
__global__ __launch_bounds__(256)
void convW_kernel(const float* __restrict__ Wf, const float* __restrict__ Wb)
{
    const int nt = blockIdx.x, ch = blockIdx.y, tid = threadIdx.x;
    const float* W = (nt < 4) ? Wf : Wb;
    const int nbase = (nt & 3) * 128;
#pragma unroll
    for (int it = 0; it < 8; it++) {
        int tup = tid + 256 * it;
        int lane = tup & 31;
        int kb = (tup >> 5) & 3;
        int nb = (tup >> 7) & 15;
        int n = nbase + nb * 8 + (lane >> 2);
        int k0 = ch * 64 + kb * 16 + 2 * (lane & 3);
        float2 q0 = *(const float2*)(W + (size_t)n * 256 + k0);
        float2 q1 = *(const float2*)(W + (size_t)n * 256 + k0 + 8);
        unsigned short h0a, l0a, h0b, l0b, h1a, l1a, h1b, l1b;
        split1(q0.x, h0a, l0a); split1(q0.y, h0b, l0b);
        split1(q1.x, h1a, l1a); split1(q1.y, h1b, l1b);
        uint2 hi = make_uint2(pack2(h0a, h0b), pack2(h1a, h1b));
        uint2 lo = make_uint2(pack2(l0a, l0b), pack2(l1a, l1b));
        unsigned char* dst = g_wbuf + ((size_t)(nt * 4 + ch)) * 32768
                           + ((nb * 4 + kb) * 32 + lane) * 8;
        *(uint2*)dst = hi;
        *(uint2*)(dst + 16384) = lo;
    }
}

// ---------------------------------------------------------------------------
// Layer-1 projection via mma.sync split-bf16 (HMMA.16816). Unchanged from R8.
// ---------------------------------------------------------------------------
#define GEMM_SMEM 65536

__device__ __forceinline__ void mma16816(float* c, const uint4& a, const uint2& b) {
    asm volatile(
        "mma.sync.aligned.m16n8k16.row.col.f32.bf16.bf16.f32 "
        "{%0,%1,%2,%3}, {%4,%5,%6,%7}, {%8,%9}, {%0,%1,%2,%3};"
        : "+f"(c[0]), "+f"(c[1]), "+f"(c[2]), "+f"(c[3])
        : "r"(a.x), "r"(a.y), "r"(a.z), "r"(a.w), "r"(b.x), "r"(b.y));
}

__global__ __launch_bounds__(256, 2)
void gemm1_mma_kernel(const float* __restrict__ bihf, const float* __restrict__ bhhf,
                      const float* __restrict__ bihb, const float* __restrict__ bhhb)
{
    extern __shared__ __align__(16) unsigned char smem[];
    const int nt  = blockIdx.x;
    const int mt  = blockIdx.y;
    const int tid = threadIdx.x;
    const int lane = tid & 31;
    const int w    = tid >> 5;
    const int wm   = (w >> 2) * 4;
    const int wn   = (w & 3) * 4;

    float acc[4][4][4];
#pragma unroll
    for (int i = 0; i < 4; i++)
#pragma unroll
        for (int j = 0; j < 4; j++)
#pragma unroll
            for (int r = 0; r < 4; r++) acc[i][j][r] = 0.0f;

    for (int ch = 0; ch < 4; ch++) {
        {
            const uint4* sA = (const uint4*)(g_abuf + ((size_t)(mt * 4 + ch)) * 32768);
            uint4* dA = (uint4*)smem;
#pragma unroll
            for (int i = 0; i < 8; i++) dA[tid + 256 * i] = sA[tid + 256 * i];
            const uint4* sW = (const uint4*)(g_wbuf + ((size_t)(nt * 4 + ch)) * 32768);
            uint4* dW = (uint4*)(smem + 32768);
#pragma unroll
            for (int i = 0; i < 8; i++) dW[tid + 256 * i] = sW[tid + 256 * i];
        }
        __syncthreads();

        const uint4* Ah = (const uint4*)smem;
        const uint4* Al = (const uint4*)(smem + 16384);
        const uint2* Wh = (const uint2*)(smem + 32768);
        const uint2* Wl = (const uint2*)(smem + 49152);

#pragma unroll
        for (int kb = 0; kb < 4; kb++) {
            uint4 ah[4], al[4];
            uint2 wh[4], wl[4];
#pragma unroll
            for (int i = 0; i < 4; i++) {
                int idx = ((wm + i) * 4 + kb) * 32 + lane;
                ah[i] = Ah[idx];
                al[i] = Al[idx];
            }
#pragma unroll
            for (int j = 0; j < 4; j++) {
                int idx = ((wn + j) * 4 + kb) * 32 + lane;
                wh[j] = Wh[idx];
                wl[j] = Wl[idx];
            }
#pragma unroll
            for (int i = 0; i < 4; i++)
#pragma unroll
                for (int j = 0; j < 4; j++) {
                    mma16816(acc[i][j], ah[i], wh[j]);
                    mma16816(acc[i][j], ah[i], wl[j]);
                    mma16816(acc[i][j], al[i], wh[j]);
                }
        }
        __syncthreads();
    }

    const int mrow0 = mt * 128 + (w >> 2) * 64 + (lane >> 2);
    const int ncol0 = nt * 128 + (w & 3) * 32 + 2 * (lane & 3);
#pragma unroll
    for (int j = 0; j < 4; j++) {
        int n0 = ncol0 + j * 8;
        float b0, b1;
        if (n0 < 512) { b0 = bihf[n0] + bhhf[n0]; b1 = bihf[n0 + 1] + bhhf[n0 + 1]; }
        else { b0 = bihb[n0 - 512] + bhhb[n0 - 512]; b1 = bihb[n0 - 511] + bhhb[n0 - 511]; }
#pragma unroll
        for (int i = 0; i < 4; i++) {
            int m0 = mrow0 + i * 16;
            float2 v0 = make_float2(acc[i][j][0] + b0, acc[i][j][1] + b1);
            float2 v1 = make_float2(acc[i][j][2] + b0, acc[i][j][3] + b1);
            *(float2*)(g_xp + (size_t)m0 * 1024 + n0) = v0;
            *(float2*)(g_xp + (size_t)(m0 + 8) * 1024 + n0) = v1;
        }
    }
}

// ---------------------------------------------------------------------------
// Layer-0 projection GEMM (FFMA2; K=32). Unchanged.
// ---------------------------------------------------------------------------
#define BM  128
#define BN  128
#define BKK 16

__global__ __launch_bounds__(256)
void proj_gemm_kernel(const float* __restrict__ A, int K,
                      const float* __restrict__ Wf, const float* __restrict__ Wb,
                      const float* __restrict__ bihf, const float* __restrict__ bhhf,
                      const float* __restrict__ bihb, const float* __restrict__ bhhb)
{
    __shared__ __align__(16) float As[BKK * BM];
    __shared__ __align__(16) float Ws[BKK * BN];

    const int n0 = blockIdx.x * BN;
    const int m0 = blockIdx.y * BM;

    const float* Wsel; const float* bihS; const float* bhhS; int nb;
    if (n0 < 512) { Wsel = Wf; bihS = bihf; bhhS = bhhf; nb = n0; }
    else          { Wsel = Wb; bihS = bihb; bhhS = bhhb; nb = n0 - 512; }

    const int tid = threadIdx.x;
    const int tx = tid & 15;
    const int ty = tid >> 4;

    unsigned long long acc[8][4];
#pragma unroll
    for (int i = 0; i < 8; i++)
#pragma unroll
        for (int j = 0; j < 4; j++) acc[i][j] = 0ULL;

    for (int k0 = 0; k0 < K; k0 += BKK) {
#pragma unroll
        for (int it = 0; it < 2; it++) {
            int idx = tid + it * 256;
            int r = idx >> 2, c4 = idx & 3;
            float4 a4 = *(const float4*)(A + (size_t)(m0 + r) * K + k0 + c4 * 4);
            As[(c4 * 4 + 0) * BM + r] = a4.x;
            As[(c4 * 4 + 1) * BM + r] = a4.y;
            As[(c4 * 4 + 2) * BM + r] = a4.z;
            As[(c4 * 4 + 3) * BM + r] = a4.w;
        }
#pragma unroll
        for (int it = 0; it < 2; it++) {
            int idx = tid + it * 256;
            int n = idx >> 2, c4 = idx & 3;
            float4 w4 = *(const float4*)(Wsel + (size_t)(nb + n) * K + k0 + c4 * 4);
            Ws[(c4 * 4 + 0) * BN + n] = w4.x;
            Ws[(c4 * 4 + 1) * BN + n] = w4.y;
            Ws[(c4 * 4 + 2) * BN + n] = w4.z;
            Ws[(c4 * 4 + 3) * BN + n] = w4.w;
        }
        __syncthreads();

#pragma unroll
        for (int kk = 0; kk < BKK; kk++) {
            const float* arow = As + kk * BM + ty * 8;
            float4 av0 = *(const float4*)(arow);
            float4 av1 = *(const float4*)(arow + 4);
            float av[8] = {av0.x, av0.y, av0.z, av0.w, av1.x, av1.y, av1.z, av1.w};
            unsigned long long a2[8];
#pragma unroll
            for (int i = 0; i < 8; i++) {
                unsigned int ai = __float_as_uint(av[i]);
                asm("mov.b64 %0, {%1, %1};" : "=l"(a2[i]) : "r"(ai));
            }
            const unsigned long long* wrow =
                (const unsigned long long*)(Ws + kk * BN + tx * 8);
            unsigned long long b0 = wrow[0], b1 = wrow[1], b2 = wrow[2], b3 = wrow[3];
#pragma unroll
            for (int i = 0; i < 8; i++) {
                asm("fma.rn.f32x2 %0, %1, %2, %0;" : "+l"(acc[i][0]) : "l"(a2[i]), "l"(b0));
                asm("fma.rn.f32x2 %0, %1, %2, %0;" : "+l"(acc[i][1]) : "l"(a2[i]), "l"(b1));
                asm("fma.rn.f32x2 %0, %1, %2, %0;" : "+l"(acc[i][2]) : "l"(a2[i]), "l"(b2));
                asm("fma.rn.f32x2 %0, %1, %2, %0;" : "+l"(acc[i][3]) : "l"(a2[i]), "l"(b3));
            }
        }
        __syncthreads();
    }

    float bias[8];
#pragma unroll
    for (int j = 0; j < 8; j++) {
        int n = nb + tx * 8 + j;
        bias[j] = bihS[n] + bhhS[n];
    }
#pragma unroll
    for (int i = 0; i < 8; i++) {
        float out[8];
#pragma unroll
        for (int j2 = 0; j2 < 4; j2++) {
            unsigned int lo_u, hi_u;
            asm("mov.b64 {%0, %1}, %2;" : "=r"(lo_u), "=r"(hi_u) : "l"(acc[i][j2]));
            out[2 * j2 + 0] = __uint_as_float(lo_u) + bias[2 * j2 + 0];
            out[2 * j2 + 1] = __uint_as_float(hi_u) + bias[2 * j2 + 1];
        }
        float4* dst = (float4*)(g_xp + (size_t)(m0 + ty * 8 + i) * 1024 + n0 + tx * 8);
        dst[0] = make_float4(out[0], out[1], out[2], out[3]);
        dst[1] = make_float4(out[4], out[5], out[6], out[7]);
    }
}

// ---------------------------------------------------------------------------
// LSTM recurrent scan v4.
//   256 threads; thread = (u, kh). NPREG=22 pairs/gate in regs (176 regs,
//   ~25 regs slack for ptxas LDS pipelining), 10 pairs/gate in smem (80 KB).
//   h stored TWICE per parity (copy B at +16-word skew) -> kh0/kh1 LDS.128
//   broadcasts hit disjoint banks (1 wavefront). Both kh threads run the
//   butterfly + activations (redundantly) and store their own h copy;
//   each prefetches 2 of 4 gate preacts. One __syncthreads per step.
// ---------------------------------------------------------------------------
#define NPREG 22
#define NPSM  (32 - NPREG)                  // 10
#define WSM_ULL (4 * NPSM * 256)            // 10240 ull = 80 KiB
#define HPAR 272                            // copyA words 0..127, copyB 144..271
#define SCAN_SMEM (WSM_ULL * 8 + 2 * HPAR * 4)

__global__ __launch_bounds__(256, 1)
void lstm_scan_kernel(const float* __restrict__ WhhF,
                      const float* __restrict__ WhhB,
                      int writeSeq,
                      float* __restrict__ finalOut)
{
    extern __shared__ __align__(16) float smemf[];
    unsigned long long* Wsm = (unsigned long long*)smemf;   // [4*NPSM][256]
    float* hbuf = smemf + WSM_ULL * 2;                      // [2][HPAR]

    const int b   = blockIdx.x;
    const int dir = blockIdx.y;
    const int t   = threadIdx.x;
    const int u   = t >> 1;
    const int kh  = t & 1;
    const int K0  = kh * 64;
    const float* __restrict__ Whh = dir ? WhhB : WhhF;

    unsigned long long wr[4][NPREG];
#pragma unroll
    for (int g = 0; g < 4; g++) {
        const unsigned long long* row =
            (const unsigned long long*)(Whh + (size_t)(g * 128 + u) * HID + K0);
#pragma unroll
        for (int p = 0; p < NPREG; p++) wr[g][p] = row[p];
#pragma unroll
        for (int q = 0; q < NPSM; q++)
            Wsm[(g * NPSM + q) * 256 + t] = row[NPREG + q];
    }

    for (int i = t; i < 2 * HPAR; i += 256) hbuf[i] = 0.0f;

    // gate preacts: kh0 loads gates 0,1; kh1 loads gates 2,3 (for unit u)
    const size_t xbase = (size_t)b * TT * 1024 + (size_t)dir * 512
                       + (size_t)kh * 256 + u;
    const size_t obase = (size_t)b * TT * 256 + (size_t)dir * HID + u;

    float xvA, xvB;
    {
        int t0 = dir ? (TT - 1) : 0;
        const float* xp = g_xp + xbase + (size_t)t0 * 1024;
        xvA = xp[0]; xvB = xp[128];
    }

    // read base: kh0 -> copyA words 0..63; kh1 -> copyB words 208..271
    const int rdoff = kh ? (144 + 64) : 0;
    const int wroff = kh ? (144 + u) : u;

    __syncthreads();

    float cval = 0.0f, hval = 0.0f;
    int par = 0;

    for (int s = 0; s < TT; s++) {
        const int tcur = dir ? (TT - 1 - s) : s;

        float nxA, nxB;
        {
            int sn = (s + 1 < TT) ? (s + 1) : s;
            int tn = dir ? (TT - 1 - sn) : sn;
            const float* xpn = g_xp + xbase + (size_t)tn * 1024;
            nxA = xpn[0]; nxB = xpn[128];
        }

        const float* hc = hbuf + par * HPAR + rdoff;
        unsigned long long a0 = 0ULL, a1 = 0ULL, a2 = 0ULL, a3 = 0ULL;
#pragma unroll
        for (int i = 0; i < 16; i++) {
            ulonglong2 hv = *(const ulonglong2*)(hc + 4 * i);
            unsigned long long w0a, w0b, w0c, w0d, w1a, w1b, w1c, w1d;
            if (2 * i + 1 < NPREG) {
                w0a = wr[0][2 * i];     w1a = wr[0][2 * i + 1];
                w0b = wr[1][2 * i];     w1b = wr[1][2 * i + 1];
                w0c = wr[2][2 * i];     w1c = wr[2][2 * i + 1];
                w0d = wr[3][2 * i];     w1d = wr[3][2 * i + 1];
            } else {
                int q0 = 2 * i - NPREG;
                w0a = Wsm[(0 * NPSM + q0) * 256 + t];
                w1a = Wsm[(0 * NPSM + q0 + 1) * 256 + t];
                w0b = Wsm[(1 * NPSM + q0) * 256 + t];
                w1b = Wsm[(1 * NPSM + q0 + 1) * 256 + t];
                w0c = Wsm[(2 * NPSM + q0) * 256 + t];
                w1c = Wsm[(2 * NPSM + q0 + 1) * 256 + t];
                w0d = Wsm[(3 * NPSM + q0) * 256 + t];
                w1d = Wsm[(3 * NPSM + q0 + 1) * 256 + t];
            }
            asm("fma.rn.f32x2 %0, %1, %2, %0;" : "+l"(a0) : "l"(w0a), "l"(hv.x));
            asm("fma.rn.f32x2 %0, %1, %2, %0;" : "+l"(a1) : "l"(w0b), "l"(hv.x));
            asm("fma.rn.f32x2 %0, %1, %2, %0;" : "+l"(a2) : "l"(w0c), "l"(hv.x));
            asm("fma.rn.f32x2 %0, %1, %2, %0;" : "+l"(a3) : "l"(w0d), "l"(hv.x));
            asm("fma.rn.f32x2 %0, %1, %2, %0;" : "+l"(a0) : "l"(w1a), "l"(hv.y));
            asm("fma.rn.f32x2 %0, %1, %2, %0;" : "+l"(a1) : "l"(w1b), "l"(hv.y));
            asm("fma.rn.f32x2 %0, %1, %2, %0;" : "+l"(a2) : "l"(w1c), "l"(hv.y));
            asm("fma.rn.f32x2 %0, %1, %2, %0;" : "+l"(a3) : "l"(w1d), "l"(hv.y));
        }

        float s0, s1, s2, s3;
        {
            unsigned int lo, hi;
            asm("mov.b64 {%0, %1}, %2;" : "=r"(lo), "=r"(hi) : "l"(a0));
            s0 = __uint_as_float(lo) + __uint_as_float(hi);
            asm("mov.b64 {%0, %1}, %2;" : "=r"(lo), "=r"(hi) : "l"(a1));
            s1 = __uint_as_float(lo) + __uint_as_float(hi);
            asm("mov.b64 {%0, %1}, %2;" : "=r"(lo), "=r"(hi) : "l"(a2));
            s2 = __uint_as_float(lo) + __uint_as_float(hi);
            asm("mov.b64 {%0, %1}, %2;" : "=r"(lo), "=r"(hi) : "l"(a3));
            s3 = __uint_as_float(lo) + __uint_as_float(hi);
        }
        // add own gate preacts before the butterfly (each gate added once)
        if (kh == 0) { s0 += xvA; s1 += xvB; }
        else         { s2 += xvA; s3 += xvB; }

        s0 += __shfl_xor_sync(0xffffffffu, s0, 1);
        s1 += __shfl_xor_sync(0xffffffffu, s1, 1);
        s2 += __shfl_xor_sync(0xffffffffu, s2, 1);
        s3 += __shfl_xor_sync(0xffffffffu, s3, 1);

        // both kh threads compute activations (identical results)
        {
            float iv = sigmoid_(s0);
            float fv = sigmoid_(s1);
            float gv = tanh_(s2);
            float ov = sigmoid_(s3);
            cval = fv * cval + iv * gv;
            hval = ov * tanh_(cval);
            hbuf[(par ^ 1) * HPAR + wroff] = hval;   // kh0->copyA, kh1->copyB
            if (writeSeq && kh == 0)
                g_out1[obase + (size_t)tcur * 256] = hval;
        }
        __syncthreads();

        par ^= 1;
        xvA = nxA; xvB = nxB;
    }

    if (finalOut != nullptr && kh == 0)
        finalOut[(size_t)b * 256 + (size_t)dir * HID + u] = hval;
}

// ---------------------------------------------------------------------------
// kernel_launch
// ---------------------------------------------------------------------------
extern "C" void kernel_launch(void* const* d_in, const int* in_sizes, int n_in,
                              void* d_out, int out_size)
{
    const float* x       = (const float*)d_in[0];
    const float* Wih_l0f = (const float*)d_in[1];
    const float* Whh_l0f = (const float*)d_in[2];
    const float* bih_l0f = (const float*)d_in[3];
    const float* bhh_l0f = (const float*)d_in[4];
    const float* Wih_l0b = (const float*)d_in[5];
    const float* Whh_l0b = (const float*)d_in[6];
    const float* bih_l0b = (const float*)d_in[7];
    const float* bhh_l0b = (const float*)d_in[8];
    const float* Wih_l1f = (const float*)d_in[9];
    const float* Whh_l1f = (const float*)d_in[10];
    const float* bih_l1f = (const float*)d_in[11];
    const float* bhh_l1f = (const float*)d_in[12];
    const float* Wih_l1b = (const float*)d_in[13];
    const float* Whh_l1b = (const float*)d_in[14];
    const float* bih_l1b = (const float*)d_in[15];
    const float* bhh_l1b = (const float*)d_in[16];

    float* out = (float*)d_out;

    cudaFuncSetAttribute(lstm_scan_kernel,
                         cudaFuncAttributeMaxDynamicSharedMemorySize, SCAN_SMEM);
    cudaFuncSetAttribute(gemm1_mma_kernel,
                         cudaFuncAttributeMaxDynamicSharedMemorySize, GEMM_SMEM);

    // W hi/lo fragment images for layer-1 HMMA
    convW_kernel<<<dim3(8, 4), 256>>>(Wih_l1f, Wih_l1b);

    // Layer 0 input projection (FFMA2): x[BT,32] -> g_xp[BT,1024]
    proj_gemm_kernel<<<dim3(8, BT / BM), 256>>>(x, 32,
                                                Wih_l0f, Wih_l0b,
                                                bih_l0f, bhh_l0f, bih_l0b, bhh_l0b);

    // Layer 0 scan: g_xp -> g_out1[BT,256]
    lstm_scan_kernel<<<dim3(BB, 2), 256, SCAN_SMEM>>>(
        Whh_l0f, Whh_l0b, /*writeSeq=*/1, /*finalOut=*/nullptr);

    // A hi/lo fragment images from g_out1
    convA_kernel<<<1024, 256>>>();

    // Layer 1 projection via split-bf16 mma.sync -> g_xp[BT,1024]
    gemm1_mma_kernel<<<dim3(8, 1024), 256, GEMM_SMEM>>>(
        bih_l1f, bhh_l1f, bih_l1b, bhh_l1b);

    // Layer 1 scan: g_xp -> final hidden states in d_out[64,256]
    lstm_scan_kernel<<<dim3(BB, 2), 256, SCAN_SMEM>>>(
        Whh_l1f, Whh_l1b, /*writeSeq=*/0, /*finalOut=*/out);
}